// round 2
// baseline (speedup 1.0000x reference)
#include <cuda_runtime.h>
#include <math.h>

// ---------------------------------------------------------------------------
// Swin Transformer block, B=64, H=W=56, DIM=128, HEADS=4, HEAD_DIM=32, WS=7,
// SHIFT=3, N=49, NW=64, HIDDEN=512.  M_TOT = B*H*W = 200704 tokens.
//
// Pipeline (7 launches):
//   1. ln1_gather : LN(x) + cyclic shift + window partition -> ywin (window order)
//   2. qkv GEMM   : ywin @ qkv_w + qkv_b -> qkv
//   3. attention  : per (window, head) block, softmax(qk^T + bias + mask) @ v -> att
//   4. proj GEMM  : att @ proj_w + proj_b, scatter (window reverse + unshift)
//                   + residual x -> x1
//   5. ln2        : LN(x1) -> ywin (reuse)
//   6. fc1 GEMM   : ywin @ fc1_w + fc1_b, exact GELU -> hid (overlays qkv+att)
//   7. fc2 GEMM   : hid @ fc2_w + fc2_b + residual x1 -> d_out
//
// Single scratch arena, 768 floats/token (616 MB), lifetime-overlapped.
// ---------------------------------------------------------------------------

#define M_TOT 200704
#define HSCALE 0.17677669529663687f   /* 32^-0.5 */

__device__ float g_s[(size_t)M_TOT * 768];

#define P_YWIN (g_s)
#define P_QKV  (g_s + (size_t)M_TOT * 128)
#define P_ATT  (g_s + (size_t)M_TOT * 512)
#define P_X1   (g_s + (size_t)M_TOT * 640)
#define P_HID  (g_s + (size_t)M_TOT * 128)

// window-order row m -> natural token row. Both the gather (shift) and the
// scatter (unshift) reduce to (pos + 3) mod 56 here.
__device__ __forceinline__ int map_row(int m) {
    int win = m / 49;
    int t   = m - win * 49;
    int img  = win >> 6;
    int widx = win & 63;
    int tr = t / 7;
    int hs = (widx >> 3) * 7 + tr;
    int ws = (widx & 7) * 7 + (t - tr * 7);
    int hh = hs + 3; if (hh >= 56) hh -= 56;
    int ww = ws + 3; if (ww >= 56) ww -= 56;
    return img * 3136 + hh * 56 + ww;
}

// ---------------------------------------------------------------------------
// LayerNorm: one warp per token, 4 elems per lane
// ---------------------------------------------------------------------------
__device__ __forceinline__ void ln_body(const float* __restrict__ X,
                                        const float* __restrict__ g,
                                        const float* __restrict__ b,
                                        float* __restrict__ Y, bool gather) {
    int w = (int)((blockIdx.x * blockDim.x + threadIdx.x) >> 5);
    if (w >= M_TOT) return;
    int lane = threadIdx.x & 31;
    int src = gather ? map_row(w) : w;
    const float* xp = X + (size_t)src * 128;
    float v0 = xp[lane], v1 = xp[lane + 32], v2 = xp[lane + 64], v3 = xp[lane + 96];
    float s = v0 + v1 + v2 + v3;
    #pragma unroll
    for (int o = 16; o; o >>= 1) s += __shfl_xor_sync(0xffffffffu, s, o);
    float mean = s * 0.0078125f;
    float d0 = v0 - mean, d1 = v1 - mean, d2 = v2 - mean, d3 = v3 - mean;
    float vv = d0 * d0 + d1 * d1 + d2 * d2 + d3 * d3;
    #pragma unroll
    for (int o = 16; o; o >>= 1) vv += __shfl_xor_sync(0xffffffffu, vv, o);
    float rstd = rsqrtf(vv * 0.0078125f + 1e-5f);
    float* yp = Y + (size_t)w * 128;
    yp[lane]      = d0 * rstd * g[lane]      + b[lane];
    yp[lane + 32] = d1 * rstd * g[lane + 32] + b[lane + 32];
    yp[lane + 64] = d2 * rstd * g[lane + 64] + b[lane + 64];
    yp[lane + 96] = d3 * rstd * g[lane + 96] + b[lane + 96];
}

__global__ void k_ln1(const float* __restrict__ x, const float* __restrict__ g,
                      const float* __restrict__ b) {
    ln_body(x, g, b, P_YWIN, true);
}
__global__ void k_ln2(const float* __restrict__ g, const float* __restrict__ b) {
    ln_body(P_X1, g, b, P_YWIN, false);
}

// ---------------------------------------------------------------------------
// SGEMM: 128x128 tile, BK=8, 256 threads, 8x8 per thread.
// A: M x K row-major, B: K x N row-major, C: M x N row-major.
// EPI: 0 = +bias
//      1 = +bias, exact GELU
//      2 = +bias, +resid[row]
//      3 = +bias, scatter dst=map_row(row), +resid[dst]
// ---------------------------------------------------------------------------
template <int EPI>
__device__ __forceinline__ void sgemm_body(const float* __restrict__ A,
                                           const float* __restrict__ B,
                                           const float* __restrict__ bias,
                                           float* __restrict__ C,
                                           const float* __restrict__ resid,
                                           int K, int N) {
    __shared__ float As[8][128];
    __shared__ float Bs[8][128];
    int tid  = threadIdx.x;
    int row0 = blockIdx.y * 128;
    int col0 = blockIdx.x * 128;

    int arow = tid >> 1, acol = (tid & 1) * 4;   // A tile: 128 rows x 8 cols
    int brow = tid >> 5, bcol = (tid & 31) * 4;  // B tile: 8 rows x 128 cols
    int ty = tid >> 4, tx = tid & 15;

    float acc[8][8];
    #pragma unroll
    for (int i = 0; i < 8; i++)
        #pragma unroll
        for (int j = 0; j < 8; j++) acc[i][j] = 0.0f;

    const float* Aptr = A + (size_t)(row0 + arow) * K + acol;
    const float* Bptr = B + (size_t)brow * N + col0 + bcol;

    for (int k0 = 0; k0 < K; k0 += 8) {
        float4 av = *(const float4*)(Aptr + k0);
        As[acol + 0][arow] = av.x;
        As[acol + 1][arow] = av.y;
        As[acol + 2][arow] = av.z;
        As[acol + 3][arow] = av.w;
        float4 bv = *(const float4*)(Bptr + (size_t)k0 * N);
        *(float4*)&Bs[brow][bcol] = bv;
        __syncthreads();
        #pragma unroll
        for (int k = 0; k < 8; k++) {
            float a[8], bb[8];
            float4 a0 = *(const float4*)&As[k][ty * 8];
            float4 a1 = *(const float4*)&As[k][ty * 8 + 4];
            float4 b0 = *(const float4*)&Bs[k][tx * 8];
            float4 b1 = *(const float4*)&Bs[k][tx * 8 + 4];
            a[0]=a0.x; a[1]=a0.y; a[2]=a0.z; a[3]=a0.w;
            a[4]=a1.x; a[5]=a1.y; a[6]=a1.z; a[7]=a1.w;
            bb[0]=b0.x; bb[1]=b0.y; bb[2]=b0.z; bb[3]=b0.w;
            bb[4]=b1.x; bb[5]=b1.y; bb[6]=b1.z; bb[7]=b1.w;
            #pragma unroll
            for (int i = 0; i < 8; i++)
                #pragma unroll
                for (int j = 0; j < 8; j++)
                    acc[i][j] = fmaf(a[i], bb[j], acc[i][j]);
        }
        __syncthreads();
    }

    #pragma unroll
    for (int i = 0; i < 8; i++) {
        int row = row0 + ty * 8 + i;
        int cbase = col0 + tx * 8;
        size_t orow;
        if (EPI == 3) {
            orow = (size_t)map_row(row) * N;
        } else {
            orow = (size_t)row * N;
        }
        #pragma unroll
        for (int j = 0; j < 8; j++) {
            int col = cbase + j;
            float v = acc[i][j] + bias[col];
            if (EPI == 1) {
                v = 0.5f * v * (1.0f + erff(v * 0.70710678118654752f));
            } else if (EPI == 2) {
                v += resid[(size_t)row * N + col];
            } else if (EPI == 3) {
                v += resid[orow + col];
            }
            C[orow + col] = v;
        }
    }
}

__global__ void __launch_bounds__(256) k_qkv(const float* __restrict__ w,
                                             const float* __restrict__ b) {
    sgemm_body<0>(P_YWIN, w, b, P_QKV, nullptr, 128, 384);
}
__global__ void __launch_bounds__(256) k_proj(const float* __restrict__ w,
                                              const float* __restrict__ b,
                                              const float* __restrict__ x) {
    sgemm_body<3>(P_ATT, w, b, P_X1, x, 128, 128);
}
__global__ void __launch_bounds__(256) k_fc1(const float* __restrict__ w,
                                             const float* __restrict__ b) {
    sgemm_body<1>(P_YWIN, w, b, P_HID, nullptr, 128, 512);
}
__global__ void __launch_bounds__(256) k_fc2(const float* __restrict__ w,
                                             const float* __restrict__ b,
                                             float* __restrict__ out) {
    sgemm_body<2>(P_HID, w, b, out, P_X1, 512, 128);
}

// ---------------------------------------------------------------------------
// Attention: one block per (window, head). N=49 tokens, head_dim=32.
// Relative-position bias and shifted-window mask computed inline.
// ---------------------------------------------------------------------------
__global__ void __launch_bounds__(128) k_attn(const float* __restrict__ rpb) {
    __shared__ float qs[49][33], ks[49][33], vs[49][33];
    __shared__ float sc[49][52];
    __shared__ float bias_s[169];
    __shared__ int   rid[49];

    int wh   = blockIdx.x;
    int win  = wh >> 2;
    int head = wh & 3;
    int widx = win & 63;
    int wi = widx >> 3, wj = widx & 7;
    int tid = threadIdx.x;

    const float* base = P_QKV + (size_t)(win * 49) * 384 + head * 32;
    for (int idx = tid; idx < 49 * 32; idx += 128) {
        int t = idx >> 5, d = idx & 31;
        const float* p = base + (size_t)t * 384 + d;
        qs[t][d] = p[0] * HSCALE;
        ks[t][d] = p[128];
        vs[t][d] = p[256];
    }
    for (int idx = tid; idx < 169; idx += 128) bias_s[idx] = rpb[idx * 4 + head];
    if (tid < 49) {
        int r = wi * 7 + tid / 7;
        int c = wj * 7 + tid % 7;
        int rh = (r < 49) ? 0 : ((r < 53) ? 1 : 2);
        int rw = (c < 49) ? 0 : ((c < 53) ? 1 : 2);
        rid[tid] = rh * 3 + rw;
    }
    __syncthreads();

    for (int idx = tid; idx < 49 * 49; idx += 128) {
        int i = idx / 49, j = idx - i * 49;
        float s = 0.0f;
        #pragma unroll
        for (int d = 0; d < 32; d++) s = fmaf(qs[i][d], ks[j][d], s);
        int dr = i / 7 - j / 7 + 6;
        int dc = i % 7 - j % 7 + 6;
        s += bias_s[dr * 13 + dc];
        if (rid[i] != rid[j]) s -= 100.0f;
        sc[i][j] = s;
    }
    __syncthreads();

    if (tid < 49) {
        float mx = -1e30f;
        #pragma unroll 7
        for (int j = 0; j < 49; j++) mx = fmaxf(mx, sc[tid][j]);
        float sum = 0.0f;
        #pragma unroll 7
        for (int j = 0; j < 49; j++) {
            float e = __expf(sc[tid][j] - mx);
            sc[tid][j] = e;
            sum += e;
        }
        float inv = 1.0f / sum;
        #pragma unroll 7
        for (int j = 0; j < 49; j++) sc[tid][j] *= inv;
    }
    __syncthreads();

    for (int idx = tid; idx < 49 * 32; idx += 128) {
        int i = idx >> 5, d = idx & 31;
        float s = 0.0f;
        #pragma unroll 7
        for (int j = 0; j < 49; j++) s = fmaf(sc[i][j], vs[j][d], s);
        P_ATT[(size_t)(win * 49 + i) * 128 + head * 32 + d] = s;
    }
}

// ---------------------------------------------------------------------------
extern "C" void kernel_launch(void* const* d_in, const int* in_sizes, int n_in,
                              void* d_out, int out_size) {
    const float* x      = (const float*)d_in[0];
    const float* n1g    = (const float*)d_in[1];
    const float* n1b    = (const float*)d_in[2];
    const float* qkv_w  = (const float*)d_in[3];
    const float* qkv_b  = (const float*)d_in[4];
    const float* rpb    = (const float*)d_in[5];
    const float* proj_w = (const float*)d_in[6];
    const float* proj_b = (const float*)d_in[7];
    const float* n2g    = (const float*)d_in[8];
    const float* n2b    = (const float*)d_in[9];
    const float* fc1_w  = (const float*)d_in[10];
    const float* fc1_b  = (const float*)d_in[11];
    const float* fc2_w  = (const float*)d_in[12];
    const float* fc2_b  = (const float*)d_in[13];
    float* out = (float*)d_out;

    const int LN_BLOCKS = M_TOT / 8;          // 8 warps (tokens) per 256-thread block
    k_ln1<<<LN_BLOCKS, 256>>>(x, n1g, n1b);
    k_qkv<<<dim3(3, M_TOT / 128), 256>>>(qkv_w, qkv_b);
    k_attn<<<(M_TOT / 49) * 4, 128>>>(rpb);
    k_proj<<<dim3(1, M_TOT / 128), 256>>>(proj_w, proj_b, x);
    k_ln2<<<LN_BLOCKS, 256>>>(n2g, n2b);
    k_fc1<<<dim3(4, M_TOT / 128), 256>>>(fc1_w, fc1_b);
    k_fc2<<<dim3(1, M_TOT / 128), 256>>>(fc2_w, fc2_b, out);
}

// round 5
// speedup vs baseline: 1.9281x; 1.9281x over previous
#include <cuda_runtime.h>
#include <math.h>
#include <stdint.h>

// ---------------------------------------------------------------------------
// Swin Transformer block, B=64, H=W=56, DIM=128, HEADS=4, HEAD_DIM=32, WS=7,
// SHIFT=3, N=49, NW=64, HIDDEN=512.  M_TOT = B*H*W = 200704 tokens.
//
// Pipeline (7 launches):
//   1. ln1_gather : LN(x) + cyclic shift + window partition -> ywin
//   2. qkv GEMM   : ywin @ qkv_w + qkv_b -> qkv              [tf32 tensor core]
//   3. attention  : per (window, head) softmax(qk^T+bias+mask) @ v -> att
//   4. proj GEMM  : att @ proj_w + b, scatter + resid x -> x1 [tf32 tensor core]
//   5. ln2        : LN(x1) -> ywin
//   6. fc1 GEMM   : ywin @ fc1_w + b, exact GELU -> hid       [tf32 tensor core]
//   7. fc2 GEMM   : hid @ fc2_w + b + resid x1 -> d_out       [tf32 tensor core]
// ---------------------------------------------------------------------------

#define M_TOT 200704
#define HSCALE 0.17677669529663687f   /* 32^-0.5 */

__device__ float g_s[(size_t)M_TOT * 768];

#define P_YWIN (g_s)
#define P_QKV  (g_s + (size_t)M_TOT * 128)
#define P_ATT  (g_s + (size_t)M_TOT * 512)
#define P_X1   (g_s + (size_t)M_TOT * 640)
#define P_HID  (g_s + (size_t)M_TOT * 128)

// window-order row m -> natural token row (shift and unshift are both +3 mod 56)
__device__ __forceinline__ int map_row(int m) {
    int win = m / 49;
    int t   = m - win * 49;
    int img  = win >> 6;
    int widx = win & 63;
    int tr = t / 7;
    int hs = (widx >> 3) * 7 + tr;
    int ws = (widx & 7) * 7 + (t - tr * 7);
    int hh = hs + 3; if (hh >= 56) hh -= 56;
    int ww = ws + 3; if (ww >= 56) ww -= 56;
    return img * 3136 + hh * 56 + ww;
}

// ---------------------------------------------------------------------------
// LayerNorm: one warp per token, 4 elems per lane
// ---------------------------------------------------------------------------
__device__ __forceinline__ void ln_body(const float* __restrict__ X,
                                        const float* __restrict__ g,
                                        const float* __restrict__ b,
                                        float* __restrict__ Y, bool gather) {
    int w = (int)((blockIdx.x * blockDim.x + threadIdx.x) >> 5);
    if (w >= M_TOT) return;
    int lane = threadIdx.x & 31;
    int src = gather ? map_row(w) : w;
    const float* xp = X + (size_t)src * 128;
    float v0 = xp[lane], v1 = xp[lane + 32], v2 = xp[lane + 64], v3 = xp[lane + 96];
    float s = v0 + v1 + v2 + v3;
    #pragma unroll
    for (int o = 16; o; o >>= 1) s += __shfl_xor_sync(0xffffffffu, s, o);
    float mean = s * 0.0078125f;
    float d0 = v0 - mean, d1 = v1 - mean, d2 = v2 - mean, d3 = v3 - mean;
    float vv = d0 * d0 + d1 * d1 + d2 * d2 + d3 * d3;
    #pragma unroll
    for (int o = 16; o; o >>= 1) vv += __shfl_xor_sync(0xffffffffu, vv, o);
    float rstd = rsqrtf(vv * 0.0078125f + 1e-5f);
    float* yp = Y + (size_t)w * 128;
    yp[lane]      = d0 * rstd * g[lane]      + b[lane];
    yp[lane + 32] = d1 * rstd * g[lane + 32] + b[lane + 32];
    yp[lane + 64] = d2 * rstd * g[lane + 64] + b[lane + 64];
    yp[lane + 96] = d3 * rstd * g[lane + 96] + b[lane + 96];
}

__global__ void k_ln1(const float* __restrict__ x, const float* __restrict__ g,
                      const float* __restrict__ b) {
    ln_body(x, g, b, P_YWIN, true);
}
__global__ void k_ln2(const float* __restrict__ g, const float* __restrict__ b) {
    ln_body(P_X1, g, b, P_YWIN, false);
}

// ---------------------------------------------------------------------------
// tf32 tensor-core GEMM. 128x128 tile, BK=16, 256 threads (8 warps, 4x2 grid),
// warp tile 32x64 = 2x8 m16n8k8 atoms. Double-buffered smem, register
// prefetch, one __syncthreads per k-iteration.
//   As[m][k] pad-20 : staging v4 stores AND fragment loads conflict-free
//   Bs[k][n] pad+8  : same
// EPI: 0 = +bias
//      1 = +bias, exact GELU
//      2 = +bias, +resid[row]
//      3 = +bias, scatter dst=map_row(row), +resid[dst]
// ---------------------------------------------------------------------------
__device__ __forceinline__ uint32_t f2tf(float f) {
    uint32_t u;
    asm("cvt.rna.tf32.f32 %0, %1;" : "=r"(u) : "f"(f));
    return u;
}

__device__ __forceinline__ void mma_tf32(float* c, const uint32_t* a, const uint32_t* b) {
    asm volatile(
        "mma.sync.aligned.m16n8k8.row.col.f32.tf32.tf32.f32 "
        "{%0,%1,%2,%3}, {%4,%5,%6,%7}, {%8,%9}, {%0,%1,%2,%3};"
        : "+f"(c[0]), "+f"(c[1]), "+f"(c[2]), "+f"(c[3])
        : "r"(a[0]), "r"(a[1]), "r"(a[2]), "r"(a[3]), "r"(b[0]), "r"(b[1]));
}

template <int EPI>
__device__ __forceinline__ void tgemm_body(const float* __restrict__ A,
                                           const float* __restrict__ B,
                                           const float* __restrict__ bias,
                                           float* __restrict__ C,
                                           const float* __restrict__ resid,
                                           int K, int N) {
    __shared__ uint32_t As[2][128][20];
    __shared__ uint32_t Bs[2][16][136];

    int tid  = threadIdx.x;
    int row0 = blockIdx.y * 128;
    int col0 = blockIdx.x * 128;
    int lane = tid & 31;
    int wid  = tid >> 5;
    int gid  = lane >> 2;        // 0..7
    int tig  = lane & 3;         // 0..3
    int wrow = wid >> 1;         // 0..3  (32-row band)
    int wcol = wid & 1;          // 0..1  (64-col band)

    int arow = tid >> 2;         // 0..63
    int acol = (tid & 3) << 2;   // 0,4,8,12
    int brow = tid >> 5;         // 0..7
    int bcol = lane << 2;        // 0..124

    const float* Ap0 = A + (size_t)(row0 + arow) * K + acol;
    const float* Ap1 = Ap0 + (size_t)64 * K;
    const float* Bp0 = B + (size_t)brow * N + col0 + bcol;
    const float* Bp1 = Bp0 + (size_t)8 * N;

    float acc[2][8][4];
    #pragma unroll
    for (int ma = 0; ma < 2; ma++)
        #pragma unroll
        for (int na = 0; na < 8; na++)
            #pragma unroll
            for (int q = 0; q < 4; q++) acc[ma][na][q] = 0.0f;

    // stage first tile
    {
        float4 a0 = *(const float4*)(Ap0);
        float4 a1 = *(const float4*)(Ap1);
        float4 b0 = *(const float4*)(Bp0);
        float4 b1 = *(const float4*)(Bp1);
        As[0][arow][acol+0] = f2tf(a0.x); As[0][arow][acol+1] = f2tf(a0.y);
        As[0][arow][acol+2] = f2tf(a0.z); As[0][arow][acol+3] = f2tf(a0.w);
        As[0][arow+64][acol+0] = f2tf(a1.x); As[0][arow+64][acol+1] = f2tf(a1.y);
        As[0][arow+64][acol+2] = f2tf(a1.z); As[0][arow+64][acol+3] = f2tf(a1.w);
        Bs[0][brow][bcol+0] = f2tf(b0.x); Bs[0][brow][bcol+1] = f2tf(b0.y);
        Bs[0][brow][bcol+2] = f2tf(b0.z); Bs[0][brow][bcol+3] = f2tf(b0.w);
        Bs[0][brow+8][bcol+0] = f2tf(b1.x); Bs[0][brow+8][bcol+1] = f2tf(b1.y);
        Bs[0][brow+8][bcol+2] = f2tf(b1.z); Bs[0][brow+8][bcol+3] = f2tf(b1.w);
    }
    __syncthreads();

    int nIter = K >> 4;
    for (int it = 0; it < nIter; it++) {
        int buf = it & 1;
        float4 na0, na1, nb0, nb1;
        bool more = (it + 1 < nIter);
        if (more) {
            int k0 = (it + 1) << 4;
            na0 = *(const float4*)(Ap0 + k0);
            na1 = *(const float4*)(Ap1 + k0);
            nb0 = *(const float4*)(Bp0 + (size_t)k0 * N);
            nb1 = *(const float4*)(Bp1 + (size_t)k0 * N);
        }

        #pragma unroll
        for (int kc = 0; kc < 16; kc += 8) {
            uint32_t af[2][4], bf[8][2];
            #pragma unroll
            for (int ma = 0; ma < 2; ma++) {
                int mb = wrow * 32 + ma * 16 + gid;
                af[ma][0] = As[buf][mb    ][kc + tig];
                af[ma][1] = As[buf][mb + 8][kc + tig];
                af[ma][2] = As[buf][mb    ][kc + tig + 4];
                af[ma][3] = As[buf][mb + 8][kc + tig + 4];
            }
            #pragma unroll
            for (int na = 0; na < 8; na++) {
                int nb = wcol * 64 + na * 8 + gid;
                bf[na][0] = Bs[buf][kc + tig    ][nb];
                bf[na][1] = Bs[buf][kc + tig + 4][nb];
            }
            #pragma unroll
            for (int ma = 0; ma < 2; ma++)
                #pragma unroll
                for (int na = 0; na < 8; na++)
                    mma_tf32(acc[ma][na], af[ma], bf[na]);
        }

        if (more) {
            int nb_ = buf ^ 1;
            As[nb_][arow][acol+0] = f2tf(na0.x); As[nb_][arow][acol+1] = f2tf(na0.y);
            As[nb_][arow][acol+2] = f2tf(na0.z); As[nb_][arow][acol+3] = f2tf(na0.w);
            As[nb_][arow+64][acol+0] = f2tf(na1.x); As[nb_][arow+64][acol+1] = f2tf(na1.y);
            As[nb_][arow+64][acol+2] = f2tf(na1.z); As[nb_][arow+64][acol+3] = f2tf(na1.w);
            Bs[nb_][brow][bcol+0] = f2tf(nb0.x); Bs[nb_][brow][bcol+1] = f2tf(nb0.y);
            Bs[nb_][brow][bcol+2] = f2tf(nb0.z); Bs[nb_][brow][bcol+3] = f2tf(nb0.w);
            Bs[nb_][brow+8][bcol+0] = f2tf(nb1.x); Bs[nb_][brow+8][bcol+1] = f2tf(nb1.y);
            Bs[nb_][brow+8][bcol+2] = f2tf(nb1.z); Bs[nb_][brow+8][bcol+3] = f2tf(nb1.w);
            __syncthreads();
        }
    }

    // epilogue: each thread owns (2 m-atoms) x (8 n-atoms) x {2 rows, 2 cols}
    #pragma unroll
    for (int ma = 0; ma < 2; ma++) {
        int r = row0 + wrow * 32 + ma * 16 + gid;
        size_t or0, or1;
        if (EPI == 3) {
            or0 = (size_t)map_row(r) * N;
            or1 = (size_t)map_row(r + 8) * N;
        } else {
            or0 = (size_t)r * N;
            or1 = or0 + (size_t)8 * N;
        }
        #pragma unroll
        for (int na = 0; na < 8; na++) {
            int c = col0 + wcol * 64 + na * 8 + tig * 2;
            float b0v = bias[c], b1v = bias[c + 1];
            float v00 = acc[ma][na][0] + b0v;
            float v01 = acc[ma][na][1] + b1v;
            float v10 = acc[ma][na][2] + b0v;
            float v11 = acc[ma][na][3] + b1v;
            if (EPI == 1) {
                v00 = 0.5f * v00 * (1.0f + erff(v00 * 0.70710678118654752f));
                v01 = 0.5f * v01 * (1.0f + erff(v01 * 0.70710678118654752f));
                v10 = 0.5f * v10 * (1.0f + erff(v10 * 0.70710678118654752f));
                v11 = 0.5f * v11 * (1.0f + erff(v11 * 0.70710678118654752f));
            } else if (EPI == 2 || EPI == 3) {
                v00 += resid[or0 + c];     v01 += resid[or0 + c + 1];
                v10 += resid[or1 + c];     v11 += resid[or1 + c + 1];
            }
            float2 lo = make_float2(v00, v01);
            float2 hi = make_float2(v10, v11);
            *(float2*)&C[or0 + c] = lo;
            *(float2*)&C[or1 + c] = hi;
        }
    }
}

__global__ void __launch_bounds__(256) k_qkv(const float* __restrict__ w,
                                             const float* __restrict__ b) {
    tgemm_body<0>(P_YWIN, w, b, P_QKV, nullptr, 128, 384);
}
__global__ void __launch_bounds__(256) k_proj(const float* __restrict__ w,
                                              const float* __restrict__ b,
                                              const float* __restrict__ x) {
    tgemm_body<3>(P_ATT, w, b, P_X1, x, 128, 128);
}
__global__ void __launch_bounds__(256) k_fc1(const float* __restrict__ w,
                                             const float* __restrict__ b) {
    tgemm_body<1>(P_YWIN, w, b, P_HID, nullptr, 128, 512);
}
__global__ void __launch_bounds__(256) k_fc2(const float* __restrict__ w,
                                             const float* __restrict__ b,
                                             float* __restrict__ out) {
    tgemm_body<2>(P_HID, w, b, out, P_X1, 512, 128);
}

// ---------------------------------------------------------------------------
// Attention: one block per (window, head). N=49 tokens, head_dim=32.
// Relative-position bias and shifted-window mask computed inline.
// ---------------------------------------------------------------------------
__global__ void __launch_bounds__(128) k_attn(const float* __restrict__ rpb) {
    __shared__ float qs[49][33], ks[49][33], vs[49][33];
    __shared__ float sc[49][52];
    __shared__ float bias_s[169];
    __shared__ int   rid[49];

    int wh   = blockIdx.x;
    int win  = wh >> 2;
    int head = wh & 3;
    int widx = win & 63;
    int wi = widx >> 3, wj = widx & 7;
    int tid = threadIdx.x;

    const float* base = P_QKV + (size_t)(win * 49) * 384 + head * 32;
    for (int idx = tid; idx < 49 * 32; idx += 128) {
        int t = idx >> 5, d = idx & 31;
        const float* p = base + (size_t)t * 384 + d;
        qs[t][d] = p[0] * HSCALE;
        ks[t][d] = p[128];
        vs[t][d] = p[256];
    }
    for (int idx = tid; idx < 169; idx += 128) bias_s[idx] = rpb[idx * 4 + head];
    if (tid < 49) {
        int r = wi * 7 + tid / 7;
        int c = wj * 7 + tid % 7;
        int rh = (r < 49) ? 0 : ((r < 53) ? 1 : 2);
        int rw = (c < 49) ? 0 : ((c < 53) ? 1 : 2);
        rid[tid] = rh * 3 + rw;
    }
    __syncthreads();

    for (int idx = tid; idx < 49 * 49; idx += 128) {
        int i = idx / 49, j = idx - i * 49;
        float s = 0.0f;
        #pragma unroll
        for (int d = 0; d < 32; d++) s = fmaf(qs[i][d], ks[j][d], s);
        int dr = i / 7 - j / 7 + 6;
        int dc = i % 7 - j % 7 + 6;
        s += bias_s[dr * 13 + dc];
        if (rid[i] != rid[j]) s -= 100.0f;
        sc[i][j] = s;
    }
    __syncthreads();

    if (tid < 49) {
        float mx = -1e30f;
        #pragma unroll 7
        for (int j = 0; j < 49; j++) mx = fmaxf(mx, sc[tid][j]);
        float sum = 0.0f;
        #pragma unroll 7
        for (int j = 0; j < 49; j++) {
            float e = __expf(sc[tid][j] - mx);
            sc[tid][j] = e;
            sum += e;
        }
        float inv = 1.0f / sum;
        #pragma unroll 7
        for (int j = 0; j < 49; j++) sc[tid][j] *= inv;
    }
    __syncthreads();

    for (int idx = tid; idx < 49 * 32; idx += 128) {
        int i = idx >> 5, d = idx & 31;
        float s = 0.0f;
        #pragma unroll 7
        for (int j = 0; j < 49; j++) s = fmaf(sc[i][j], vs[j][d], s);
        P_ATT[(size_t)(win * 49 + i) * 128 + head * 32 + d] = s;
    }
}

// ---------------------------------------------------------------------------
extern "C" void kernel_launch(void* const* d_in, const int* in_sizes, int n_in,
                              void* d_out, int out_size) {
    const float* x      = (const float*)d_in[0];
    const float* n1g    = (const float*)d_in[1];
    const float* n1b    = (const float*)d_in[2];
    const float* qkv_w  = (const float*)d_in[3];
    const float* qkv_b  = (const float*)d_in[4];
    const float* rpb    = (const float*)d_in[5];
    const float* proj_w = (const float*)d_in[6];
    const float* proj_b = (const float*)d_in[7];
    const float* n2g    = (const float*)d_in[8];
    const float* n2b    = (const float*)d_in[9];
    const float* fc1_w  = (const float*)d_in[10];
    const float* fc1_b  = (const float*)d_in[11];
    const float* fc2_w  = (const float*)d_in[12];
    const float* fc2_b  = (const float*)d_in[13];
    float* out = (float*)d_out;

    const int LN_BLOCKS = M_TOT / 8;          // 8 warps (tokens) per 256-thread block
    k_ln1<<<LN_BLOCKS, 256>>>(x, n1g, n1b);
    k_qkv<<<dim3(3, M_TOT / 128), 256>>>(qkv_w, qkv_b);
    k_attn<<<(M_TOT / 49) * 4, 128>>>(rpb);
    k_proj<<<dim3(1, M_TOT / 128), 256>>>(proj_w, proj_b, x);
    k_ln2<<<LN_BLOCKS, 256>>>(n2g, n2b);
    k_fc1<<<dim3(4, M_TOT / 128), 256>>>(fc1_w, fc1_b);
    k_fc2<<<dim3(1, M_TOT / 128), 256>>>(fc2_w, fc2_b, out);
}

// round 7
// speedup vs baseline: 2.2570x; 1.1706x over previous
#include <cuda_runtime.h>
#include <cuda_bf16.h>
#include <math.h>
#include <stdint.h>

// ---------------------------------------------------------------------------
// Swin Transformer block, B=64, H=W=56, DIM=128, HEADS=4, HEAD_DIM=32, WS=7,
// SHIFT=3, N=49, NW=64, HIDDEN=512.  M_TOT = 200704 tokens.
//
// bf16 intermediates (ywin/qkv/att/hid), fp32 state (x, x1, out).
// GEMMs: bf16 m16n8k16 tensor cores, fp32 accumulate.
//
//   1. ln1_gather : LN(x) + shift + window partition -> ywin (bf16)
//   2. qkv GEMM   : ywin @ qkv_w + b -> qkv (bf16)
//   3. attention  : softmax(qk^T+bias+mask) @ v -> att (bf16)
//   4. proj GEMM  : att @ proj_w + b, scatter + resid x -> x1 (fp32)
//   5. ln2        : LN(x1) -> ywin (bf16)
//   6. fc1 GEMM   : ywin @ fc1_w + b, exact GELU -> hid (bf16, overlays qkv+att)
//   7. fc2 GEMM   : hid @ fc2_w + b + resid x1 -> d_out (fp32)
// ---------------------------------------------------------------------------

#define M_TOT 200704
#define HSCALE 0.17677669529663687f   /* 32^-0.5 */

// Arena: 448 floats/token = 359 MB.
//   [0,64)    ywin  bf16 M*128
//   [64,256)  qkv   bf16 M*384   } overlaid by hid bf16 M*512 after proj
//   [256,320) att   bf16 M*128   }
//   [320,448) x1    fp32 M*128
__device__ float g_s[(size_t)M_TOT * 448];

#define P_YWIN ((__nv_bfloat16*)(g_s))
#define P_QKV  ((__nv_bfloat16*)(g_s + (size_t)M_TOT * 64))
#define P_ATT  ((__nv_bfloat16*)(g_s + (size_t)M_TOT * 256))
#define P_HID  ((__nv_bfloat16*)(g_s + (size_t)M_TOT * 64))
#define P_X1   (g_s + (size_t)M_TOT * 320)

// window-order row m -> natural token row (shift and unshift are both +3 mod 56)
__device__ __forceinline__ int map_row(int m) {
    int win = m / 49;
    int t   = m - win * 49;
    int img  = win >> 6;
    int widx = win & 63;
    int tr = t / 7;
    int hs = (widx >> 3) * 7 + tr;
    int ws = (widx & 7) * 7 + (t - tr * 7);
    int hh = hs + 3; if (hh >= 56) hh -= 56;
    int ww = ws + 3; if (ww >= 56) ww -= 56;
    return img * 3136 + hh * 56 + ww;
}

// pack two floats to bf16x2, lo in low 16 bits
__device__ __forceinline__ uint32_t pack_bf2(float lo, float hi) {
    uint32_t r;
    asm("cvt.rn.bf16x2.f32 %0, %1, %2;" : "=r"(r) : "f"(hi), "f"(lo));
    return r;
}

// ---------------------------------------------------------------------------
// LayerNorm: one warp per token, 4 elems per lane, bf16 output
// ---------------------------------------------------------------------------
__device__ __forceinline__ void ln_body(const float* __restrict__ X,
                                        const float* __restrict__ g,
                                        const float* __restrict__ b,
                                        __nv_bfloat16* __restrict__ Y, bool gather) {
    int w = (int)((blockIdx.x * blockDim.x + threadIdx.x) >> 5);
    if (w >= M_TOT) return;
    int lane = threadIdx.x & 31;
    int src = gather ? map_row(w) : w;
    const float* xp = X + (size_t)src * 128;
    float v0 = xp[lane], v1 = xp[lane + 32], v2 = xp[lane + 64], v3 = xp[lane + 96];
    float s = v0 + v1 + v2 + v3;
    #pragma unroll
    for (int o = 16; o; o >>= 1) s += __shfl_xor_sync(0xffffffffu, s, o);
    float mean = s * 0.0078125f;
    float d0 = v0 - mean, d1 = v1 - mean, d2 = v2 - mean, d3 = v3 - mean;
    float vv = d0 * d0 + d1 * d1 + d2 * d2 + d3 * d3;
    #pragma unroll
    for (int o = 16; o; o >>= 1) vv += __shfl_xor_sync(0xffffffffu, vv, o);
    float rstd = rsqrtf(vv * 0.0078125f + 1e-5f);
    __nv_bfloat16* yp = Y + (size_t)w * 128;
    yp[lane]      = __float2bfloat16(d0 * rstd * g[lane]      + b[lane]);
    yp[lane + 32] = __float2bfloat16(d1 * rstd * g[lane + 32] + b[lane + 32]);
    yp[lane + 64] = __float2bfloat16(d2 * rstd * g[lane + 64] + b[lane + 64]);
    yp[lane + 96] = __float2bfloat16(d3 * rstd * g[lane + 96] + b[lane + 96]);
}

__global__ void k_ln1(const float* __restrict__ x, const float* __restrict__ g,
                      const float* __restrict__ b) {
    ln_body(x, g, b, P_YWIN, true);
}
__global__ void k_ln2(const float* __restrict__ g, const float* __restrict__ b) {
    ln_body(P_X1, g, b, P_YWIN, false);
}

// ---------------------------------------------------------------------------
// bf16 tensor-core GEMM. 128x128 tile, BK=16, 256 threads (8 warps, 4x2),
// warp tile 32x64 = 2x8 m16n8k16 atoms. Double-buffered smem + reg prefetch.
//   As32[m][k2] stride-12 : packed bf16x2 along k; frag loads conflict-free
//   Bs32[k2][n] stride-136: pre-packed k-pairs per n; frag loads conflict-free
// A: bf16 [M][K] gmem.  B: fp32 [K][N] gmem (weights, converted on stage).
// EPI: 0 = +bias -> bf16
//      1 = +bias, exact GELU -> bf16
//      2 = +bias, +resid[row] -> fp32
//      3 = +bias, scatter dst=map_row(row), +resid[dst] -> fp32
// ---------------------------------------------------------------------------
__device__ __forceinline__ void mma_bf16(float* c, const uint32_t* a, const uint32_t* b) {
    asm volatile(
        "mma.sync.aligned.m16n8k16.row.col.f32.bf16.bf16.f32 "
        "{%0,%1,%2,%3}, {%4,%5,%6,%7}, {%8,%9}, {%0,%1,%2,%3};"
        : "+f"(c[0]), "+f"(c[1]), "+f"(c[2]), "+f"(c[3])
        : "r"(a[0]), "r"(a[1]), "r"(a[2]), "r"(a[3]), "r"(b[0]), "r"(b[1]));
}

template <int EPI, typename CT>
__device__ __forceinline__ void tgemm_body(const __nv_bfloat16* __restrict__ A,
                                           const float* __restrict__ B,
                                           const float* __restrict__ bias,
                                           CT* __restrict__ C,
                                           const float* __restrict__ resid,
                                           int K, int N) {
    __shared__ uint32_t As[2][128][12];   // [m][k2] packed bf16x2
    __shared__ uint32_t Bs[2][8][136];    // [k2][n] packed bf16x2

    int tid  = threadIdx.x;
    int row0 = blockIdx.y * 128;
    int col0 = blockIdx.x * 128;
    int lane = tid & 31;
    int wid  = tid >> 5;
    int gid  = lane >> 2;        // 0..7
    int tig  = lane & 3;         // 0..3
    int wrow = wid >> 1;         // 0..3  (32-row band)
    int wcol = wid & 1;          // 0..1  (64-col band)

    // A staging: 256 threads x 8 bf16 (uint4) = full 128x16 tile
    int arow = tid >> 1;            // 0..127
    int acol = (tid & 1) * 4;       // uint32 col: 0 or 4
    const __nv_bfloat16* Abase = A + (size_t)(row0 + arow) * K + (tid & 1) * 8;

    // B staging: thread loads rows 2*bk, 2*bk+1, packs pairs
    int bk = tid >> 5;              // 0..7
    int bn = (tid & 31) * 4;
    const float* Bp0 = B + (size_t)(2 * bk) * N + col0 + bn;
    const float* Bp1 = Bp0 + N;

    float acc[2][8][4];
    #pragma unroll
    for (int ma = 0; ma < 2; ma++)
        #pragma unroll
        for (int na = 0; na < 8; na++)
            #pragma unroll
            for (int q = 0; q < 4; q++) acc[ma][na][q] = 0.0f;

    // stage first tile
    {
        uint4 av = *(const uint4*)(Abase);
        *(uint4*)&As[0][arow][acol] = av;
        float4 r0 = *(const float4*)(Bp0);
        float4 r1 = *(const float4*)(Bp1);
        uint4 bv;
        bv.x = pack_bf2(r0.x, r1.x); bv.y = pack_bf2(r0.y, r1.y);
        bv.z = pack_bf2(r0.z, r1.z); bv.w = pack_bf2(r0.w, r1.w);
        *(uint4*)&Bs[0][bk][bn] = bv;
    }
    __syncthreads();

    int nIter = K >> 4;
    for (int it = 0; it < nIter; it++) {
        int buf = it & 1;
        uint4 nav; float4 nr0, nr1;
        bool more = (it + 1 < nIter);
        if (more) {
            int k0 = (it + 1) << 4;
            nav = *(const uint4*)(Abase + k0);
            nr0 = *(const float4*)(Bp0 + (size_t)k0 * N);
            nr1 = *(const float4*)(Bp1 + (size_t)k0 * N);
        }

        uint32_t af[2][4], bf[8][2];
        #pragma unroll
        for (int ma = 0; ma < 2; ma++) {
            int mb = wrow * 32 + ma * 16 + gid;
            af[ma][0] = As[buf][mb    ][tig];
            af[ma][1] = As[buf][mb + 8][tig];
            af[ma][2] = As[buf][mb    ][tig + 4];
            af[ma][3] = As[buf][mb + 8][tig + 4];
        }
        #pragma unroll
        for (int na = 0; na < 8; na++) {
            int nb = wcol * 64 + na * 8 + gid;
            bf[na][0] = Bs[buf][tig    ][nb];
            bf[na][1] = Bs[buf][tig + 4][nb];
        }
        #pragma unroll
        for (int ma = 0; ma < 2; ma++)
            #pragma unroll
            for (int na = 0; na < 8; na++)
                mma_bf16(acc[ma][na], af[ma], bf[na]);

        if (more) {
            int nb_ = buf ^ 1;
            *(uint4*)&As[nb_][arow][acol] = nav;
            uint4 bv;
            bv.x = pack_bf2(nr0.x, nr1.x); bv.y = pack_bf2(nr0.y, nr1.y);
            bv.z = pack_bf2(nr0.z, nr1.z); bv.w = pack_bf2(nr0.w, nr1.w);
            *(uint4*)&Bs[nb_][bk][bn] = bv;
            __syncthreads();
        }
    }

    // epilogue: (2 m-atoms) x (8 n-atoms) x {rows r, r+8} x {cols c, c+1}
    #pragma unroll
    for (int ma = 0; ma < 2; ma++) {
        int r = row0 + wrow * 32 + ma * 16 + gid;
        size_t or0, or1;
        if (EPI == 3) {
            or0 = (size_t)map_row(r) * N;
            or1 = (size_t)map_row(r + 8) * N;
        } else {
            or0 = (size_t)r * N;
            or1 = or0 + (size_t)8 * N;
        }
        #pragma unroll
        for (int na = 0; na < 8; na++) {
            int c = col0 + wcol * 64 + na * 8 + tig * 2;
            float b0v = bias[c], b1v = bias[c + 1];
            float v00 = acc[ma][na][0] + b0v;
            float v01 = acc[ma][na][1] + b1v;
            float v10 = acc[ma][na][2] + b0v;
            float v11 = acc[ma][na][3] + b1v;
            if (EPI == 1) {
                v00 = 0.5f * v00 * (1.0f + erff(v00 * 0.70710678118654752f));
                v01 = 0.5f * v01 * (1.0f + erff(v01 * 0.70710678118654752f));
                v10 = 0.5f * v10 * (1.0f + erff(v10 * 0.70710678118654752f));
                v11 = 0.5f * v11 * (1.0f + erff(v11 * 0.70710678118654752f));
            } else if (EPI == 2 || EPI == 3) {
                v00 += resid[or0 + c];     v01 += resid[or0 + c + 1];
                v10 += resid[or1 + c];     v11 += resid[or1 + c + 1];
            }
            if (sizeof(CT) == 2) {   // bf16 out: pack col pair
                *(uint32_t*)((__nv_bfloat16*)C + or0 + c) = pack_bf2(v00, v01);
                *(uint32_t*)((__nv_bfloat16*)C + or1 + c) = pack_bf2(v10, v11);
            } else {
                *(float2*)((float*)C + or0 + c) = make_float2(v00, v01);
                *(float2*)((float*)C + or1 + c) = make_float2(v10, v11);
            }
        }
    }
}

__global__ void __launch_bounds__(256) k_qkv(const float* __restrict__ w,
                                             const float* __restrict__ b) {
    tgemm_body<0>(P_YWIN, w, b, P_QKV, (const float*)nullptr, 128, 384);
}
__global__ void __launch_bounds__(256) k_proj(const float* __restrict__ w,
                                              const float* __restrict__ b,
                                              const float* __restrict__ x) {
    tgemm_body<3>(P_ATT, w, b, P_X1, x, 128, 128);
}
__global__ void __launch_bounds__(256) k_fc1(const float* __restrict__ w,
                                             const float* __restrict__ b) {
    tgemm_body<1>(P_YWIN, w, b, P_HID, (const float*)nullptr, 128, 512);
}
__global__ void __launch_bounds__(256) k_fc2(const float* __restrict__ w,
                                             const float* __restrict__ b,
                                             float* __restrict__ out) {
    tgemm_body<2>(P_HID, w, b, out, P_X1, 512, 128);
}

// ---------------------------------------------------------------------------
// Attention: one block per (window, head). N=49 tokens, head_dim=32.
// bf16 qkv in, bf16 att out; fp32 smem compute.
// ---------------------------------------------------------------------------
__global__ void __launch_bounds__(128) k_attn(const float* __restrict__ rpb) {
    __shared__ float qs[49][33], ks[49][33], vs[49][33];
    __shared__ float sc[49][52];
    __shared__ float bias_s[169];
    __shared__ int   rid[49];

    int wh   = blockIdx.x;
    int win  = wh >> 2;
    int head = wh & 3;
    int widx = win & 63;
    int wi = widx >> 3, wj = widx & 7;
    int tid = threadIdx.x;

    const __nv_bfloat16* base = P_QKV + (size_t)(win * 49) * 384 + head * 32;
    for (int idx = tid; idx < 49 * 32; idx += 128) {
        int t = idx >> 5, d = idx & 31;
        const __nv_bfloat16* p = base + (size_t)t * 384 + d;
        qs[t][d] = __bfloat162float(p[0]) * HSCALE;
        ks[t][d] = __bfloat162float(p[128]);
        vs[t][d] = __bfloat162float(p[256]);
    }
    for (int idx = tid; idx < 169; idx += 128) bias_s[idx] = rpb[idx * 4 + head];
    if (tid < 49) {
        int r = wi * 7 + tid / 7;
        int c = wj * 7 + tid % 7;
        int rh = (r < 49) ? 0 : ((r < 53) ? 1 : 2);
        int rw = (c < 49) ? 0 : ((c < 53) ? 1 : 2);
        rid[tid] = rh * 3 + rw;
    }
    __syncthreads();

    for (int idx = tid; idx < 49 * 49; idx += 128) {
        int i = idx / 49, j = idx - i * 49;
        float s = 0.0f;
        #pragma unroll
        for (int d = 0; d < 32; d++) s = fmaf(qs[i][d], ks[j][d], s);
        int dr = i / 7 - j / 7 + 6;
        int dc = i % 7 - j % 7 + 6;
        s += bias_s[dr * 13 + dc];
        if (rid[i] != rid[j]) s -= 100.0f;
        sc[i][j] = s;
    }
    __syncthreads();

    if (tid < 49) {
        float mx = -1e30f;
        #pragma unroll 7
        for (int j = 0; j < 49; j++) mx = fmaxf(mx, sc[tid][j]);
        float sum = 0.0f;
        #pragma unroll 7
        for (int j = 0; j < 49; j++) {
            float e = __expf(sc[tid][j] - mx);
            sc[tid][j] = e;
            sum += e;
        }
        float inv = 1.0f / sum;
        #pragma unroll 7
        for (int j = 0; j < 49; j++) sc[tid][j] *= inv;
    }
    __syncthreads();

    for (int idx = tid; idx < 49 * 32; idx += 128) {
        int i = idx >> 5, d = idx & 31;
        float s = 0.0f;
        #pragma unroll 7
        for (int j = 0; j < 49; j++) s = fmaf(sc[i][j], vs[j][d], s);
        P_ATT[(size_t)(win * 49 + i) * 128 + head * 32 + d] = __float2bfloat16(s);
    }
}

// ---------------------------------------------------------------------------
extern "C" void kernel_launch(void* const* d_in, const int* in_sizes, int n_in,
                              void* d_out, int out_size) {
    const float* x      = (const float*)d_in[0];
    const float* n1g    = (const float*)d_in[1];
    const float* n1b    = (const float*)d_in[2];
    const float* qkv_w  = (const float*)d_in[3];
    const float* qkv_b  = (const float*)d_in[4];
    const float* rpb    = (const float*)d_in[5];
    const float* proj_w = (const float*)d_in[6];
    const float* proj_b = (const float*)d_in[7];
    const float* n2g    = (const float*)d_in[8];
    const float* n2b    = (const float*)d_in[9];
    const float* fc1_w  = (const float*)d_in[10];
    const float* fc1_b  = (const float*)d_in[11];
    const float* fc2_w  = (const float*)d_in[12];
    const float* fc2_b  = (const float*)d_in[13];
    float* out = (float*)d_out;

    const int LN_BLOCKS = M_TOT / 8;          // 8 warps (tokens) per 256-thread block
    k_ln1<<<LN_BLOCKS, 256>>>(x, n1g, n1b);
    k_qkv<<<dim3(3, M_TOT / 128), 256>>>(qkv_w, qkv_b);
    k_attn<<<(M_TOT / 49) * 4, 128>>>(rpb);
    k_proj<<<dim3(1, M_TOT / 128), 256>>>(proj_w, proj_b, x);
    k_ln2<<<LN_BLOCKS, 256>>>(n2g, n2b);
    k_fc1<<<dim3(4, M_TOT / 128), 256>>>(fc1_w, fc1_b);
    k_fc2<<<dim3(1, M_TOT / 128), 256>>>(fc2_w, fc2_b, out);
}

// round 9
// speedup vs baseline: 2.2753x; 1.0081x over previous
#include <cuda_runtime.h>
#include <cuda_bf16.h>
#include <math.h>
#include <stdint.h>

// ---------------------------------------------------------------------------
// Swin Transformer block, B=64, H=W=56, DIM=128, HEADS=4, HEAD_DIM=32, WS=7,
// SHIFT=3, N=49, NW=64, HIDDEN=512.  M_TOT = 200704 tokens.
//
// bf16 intermediates + pre-converted n-major bf16 weights.
// GEMMs: bf16 m16n8k16, cp.async double-buffered staging, ldmatrix fragments.
//
//   0. convw      : fp32 weights -> bf16 transposed [N][K]
//   1. ln1_gather : LN(x) + shift + window partition -> ywin (bf16)
//   2. qkv GEMM   : ywin @ qkv_w + b -> qkv (bf16)
//   3. attention  : softmax(qk^T+bias+mask) @ v -> att (bf16)
//   4. proj GEMM  : att @ proj_w + b, scatter + resid x -> x1 (fp32)
//                   FUSED LN2 -> ywin (bf16)
//   5. fc1 GEMM   : ywin @ fc1_w + b, exact GELU -> hid (bf16, overlays qkv+att)
//   6. fc2 GEMM   : hid @ fc2_w + b + resid x1 -> d_out (fp32)
// ---------------------------------------------------------------------------

#define M_TOT 200704
#define HSCALE 0.17677669529663687f   /* 32^-0.5 */

// Arena: 448 floats/token = 359 MB.
__device__ float g_s[(size_t)M_TOT * 448];

#define P_YWIN ((__nv_bfloat16*)(g_s))
#define P_QKV  ((__nv_bfloat16*)(g_s + (size_t)M_TOT * 64))
#define P_ATT  ((__nv_bfloat16*)(g_s + (size_t)M_TOT * 256))
#define P_HID  ((__nv_bfloat16*)(g_s + (size_t)M_TOT * 64))
#define P_X1   (g_s + (size_t)M_TOT * 320)

// bf16 n-major weights: Wt[n][k]
__device__ __nv_bfloat16 g_wqkv[384 * 128];
__device__ __nv_bfloat16 g_wproj[128 * 128];
__device__ __nv_bfloat16 g_wfc1[512 * 128];
__device__ __nv_bfloat16 g_wfc2[128 * 512];

// window-order row m -> natural token row (shift and unshift are both +3 mod 56)
__device__ __forceinline__ int map_row(int m) {
    int win = m / 49;
    int t   = m - win * 49;
    int img  = win >> 6;
    int widx = win & 63;
    int tr = t / 7;
    int hs = (widx >> 3) * 7 + tr;
    int ws = (widx & 7) * 7 + (t - tr * 7);
    int hh = hs + 3; if (hh >= 56) hh -= 56;
    int ww = ws + 3; if (ww >= 56) ww -= 56;
    return img * 3136 + hh * 56 + ww;
}

__device__ __forceinline__ uint32_t pack_bf2(float lo, float hi) {
    uint32_t r;
    asm("cvt.rn.bf16x2.f32 %0, %1, %2;" : "=r"(r) : "f"(hi), "f"(lo));
    return r;
}

// ---------------------------------------------------------------------------
// Weight convert + transpose: W[k][n] fp32 -> Wt[n][k] bf16
// ---------------------------------------------------------------------------
__global__ void k_convw(const float* __restrict__ qkv_w, const float* __restrict__ proj_w,
                        const float* __restrict__ fc1_w, const float* __restrict__ fc2_w) {
    int i = blockIdx.x * blockDim.x + threadIdx.x;
    if (i < 49152) {                       // qkv: [128][384] -> [384][128]
        int n = i / 128, k = i % 128;
        g_wqkv[i] = __float2bfloat16(qkv_w[k * 384 + n]);
    } else if (i < 65536) {                // proj: [128][128]
        int j = i - 49152; int n = j / 128, k = j % 128;
        g_wproj[j] = __float2bfloat16(proj_w[k * 128 + n]);
    } else if (i < 131072) {               // fc1: [128][512] -> [512][128]
        int j = i - 65536; int n = j / 128, k = j % 128;
        g_wfc1[j] = __float2bfloat16(fc1_w[k * 512 + n]);
    } else if (i < 196608) {               // fc2: [512][128] -> [128][512]
        int j = i - 131072; int n = j / 512, k = j % 512;
        g_wfc2[j] = __float2bfloat16(fc2_w[k * 128 + n]);
    }
}

// ---------------------------------------------------------------------------
// LayerNorm 1: one warp per token, gather via map_row, bf16 output
// ---------------------------------------------------------------------------
__global__ void k_ln1(const float* __restrict__ X, const float* __restrict__ g,
                      const float* __restrict__ b) {
    int w = (int)((blockIdx.x * blockDim.x + threadIdx.x) >> 5);
    if (w >= M_TOT) return;
    int lane = threadIdx.x & 31;
    const float* xp = X + (size_t)map_row(w) * 128;
    float v0 = xp[lane], v1 = xp[lane + 32], v2 = xp[lane + 64], v3 = xp[lane + 96];
    float s = v0 + v1 + v2 + v3;
    #pragma unroll
    for (int o = 16; o; o >>= 1) s += __shfl_xor_sync(0xffffffffu, s, o);
    float mean = s * 0.0078125f;
    float d0 = v0 - mean, d1 = v1 - mean, d2 = v2 - mean, d3 = v3 - mean;
    float vv = d0 * d0 + d1 * d1 + d2 * d2 + d3 * d3;
    #pragma unroll
    for (int o = 16; o; o >>= 1) vv += __shfl_xor_sync(0xffffffffu, vv, o);
    float rstd = rsqrtf(vv * 0.0078125f + 1e-5f);
    __nv_bfloat16* yp = P_YWIN + (size_t)w * 128;
    yp[lane]      = __float2bfloat16(d0 * rstd * g[lane]      + b[lane]);
    yp[lane + 32] = __float2bfloat16(d1 * rstd * g[lane + 32] + b[lane + 32]);
    yp[lane + 64] = __float2bfloat16(d2 * rstd * g[lane + 64] + b[lane + 64]);
    yp[lane + 96] = __float2bfloat16(d3 * rstd * g[lane + 96] + b[lane + 96]);
}

// ---------------------------------------------------------------------------
// bf16 tensor-core GEMM. 128x128 tile, BK=16, 256 threads (8 warps 4x2),
// warp tile 32x64 = 2x8 m16n8k16. cp.async double-buffer, ldmatrix frags.
//   As[m][12 words]: rows of 16 bf16 (+pad), Bs[n][12 words]: same, n-major.
// EPI: 0 = +bias -> bf16
//      1 = +bias, exact GELU -> bf16
//      2 = +bias, +resid[row] -> fp32
//      3 = +bias, scatter dst=map_row(row), +resid[dst] -> x1 fp32
//          then fused LN -> ywin bf16
// ---------------------------------------------------------------------------
__device__ __forceinline__ void mma_bf16(float* c, const uint32_t* a, const uint32_t* b) {
    asm volatile(
        "mma.sync.aligned.m16n8k16.row.col.f32.bf16.bf16.f32 "
        "{%0,%1,%2,%3}, {%4,%5,%6,%7}, {%8,%9}, {%0,%1,%2,%3};"
        : "+f"(c[0]), "+f"(c[1]), "+f"(c[2]), "+f"(c[3])
        : "r"(a[0]), "r"(a[1]), "r"(a[2]), "r"(a[3]), "r"(b[0]), "r"(b[1]));
}

__device__ __forceinline__ void ldsm4(uint32_t* r, uint32_t a) {
    asm volatile("ldmatrix.sync.aligned.m8n8.x4.shared.b16 {%0,%1,%2,%3}, [%4];"
                 : "=r"(r[0]), "=r"(r[1]), "=r"(r[2]), "=r"(r[3]) : "r"(a));
}

__device__ __forceinline__ void cp16(uint32_t dst, const void* src) {
    asm volatile("cp.async.ca.shared.global [%0], [%1], 16;" :: "r"(dst), "l"(src));
}
#define CP_COMMIT() asm volatile("cp.async.commit_group;")
#define CP_WAIT0()  asm volatile("cp.async.wait_group 0;")

template <int EPI, typename CT>
__device__ __forceinline__ void tgemm_body(const __nv_bfloat16* __restrict__ A,
                                           const __nv_bfloat16* __restrict__ W,
                                           const float* __restrict__ bias,
                                           CT* __restrict__ C,
                                           const float* __restrict__ resid,
                                           const float* __restrict__ g2,
                                           const float* __restrict__ b2,
                                           int K, int N) {
    __shared__ uint32_t As[2][128][12];
    __shared__ uint32_t Bs[2][128][12];
    __shared__ float s_mu[128], s_sq[128];

    int tid  = threadIdx.x;
    int row0 = blockIdx.y * 128;
    int col0 = blockIdx.x * 128;
    int lane = tid & 31;
    int wid  = tid >> 5;
    int gid  = lane >> 2;
    int tig  = lane & 3;
    int wrow = wid >> 1;         // 0..3
    int wcol = wid & 1;          // 0..1

    const int BUFB = 128 * 12 * 4;   // bytes per buffer
    uint32_t asb = (uint32_t)__cvta_generic_to_shared(&As[0][0][0]);
    uint32_t bsb = (uint32_t)__cvta_generic_to_shared(&Bs[0][0][0]);

    // staging: thread -> (row tid>>1, half tid&1), 16B cp.async each
    int srow = tid >> 1, sh = tid & 1;
    const __nv_bfloat16* Ap = A + (size_t)(row0 + srow) * K + sh * 8;
    const __nv_bfloat16* Wp = W + (size_t)(col0 + srow) * K + sh * 8;
    uint32_t aDst = asb + (uint32_t)(srow * 12 + sh * 4) * 4;
    uint32_t bDst = bsb + (uint32_t)(srow * 12 + sh * 4) * 4;

    // ldmatrix lane addressing
    int rr  = lane & 7;
    int l8  = (lane >> 3) & 1;
    int l16 = lane >> 4;
    // A: row = wrow*32 + ma*16 + l8*8 + rr, word = l16*4
    uint32_t aF = asb + (uint32_t)(((wrow * 32 + l8 * 8 + rr) * 12 + l16 * 4)) * 4;
    // B: row = wcol*64 + q*16 + l16*8 + rr, word = l8*4
    uint32_t bF = bsb + (uint32_t)(((wcol * 64 + l16 * 8 + rr) * 12 + l8 * 4)) * 4;

    float acc[2][8][4];
    #pragma unroll
    for (int ma = 0; ma < 2; ma++)
        #pragma unroll
        for (int na = 0; na < 8; na++)
            #pragma unroll
            for (int q = 0; q < 4; q++) acc[ma][na][q] = 0.0f;

    // stage tile 0
    cp16(aDst, Ap);
    cp16(bDst, Wp);
    CP_COMMIT();
    CP_WAIT0();
    __syncthreads();

    int nIter = K >> 4;
    for (int it = 0; it < nIter; it++) {
        int buf = it & 1;
        bool more = (it + 1 < nIter);
        if (more) {
            int k0 = (it + 1) << 4;
            uint32_t off = (uint32_t)(buf ^ 1) * BUFB;
            cp16(aDst + off, Ap + k0);
            cp16(bDst + off, Wp + k0);
            CP_COMMIT();
        }

        uint32_t boff = (uint32_t)buf * BUFB;
        uint32_t af[2][4];
        ldsm4(af[0], aF + boff);
        ldsm4(af[1], aF + boff + 16 * 48);
        uint32_t bf[8][2];
        #pragma unroll
        for (int q = 0; q < 4; q++) {
            uint32_t bq[4];
            ldsm4(bq, bF + boff + (uint32_t)q * 16 * 48);
            bf[2 * q][0] = bq[0]; bf[2 * q][1] = bq[1];
            bf[2 * q + 1][0] = bq[2]; bf[2 * q + 1][1] = bq[3];
        }
        #pragma unroll
        for (int ma = 0; ma < 2; ma++)
            #pragma unroll
            for (int na = 0; na < 8; na++)
                mma_bf16(acc[ma][na], af[ma], bf[na]);

        if (more) {
            CP_WAIT0();
            __syncthreads();
        }
    }

    // ---------------- epilogue ----------------
    if (EPI == 3) {
        if (tid < 128) { s_mu[tid] = 0.0f; s_sq[tid] = 0.0f; }
        __syncthreads();
    }

    int dsts[2][2];
    #pragma unroll
    for (int ma = 0; ma < 2; ma++) {
        int rl0 = wrow * 32 + ma * 16 + gid;
        int r = row0 + rl0;
        size_t or0, or1;
        if (EPI == 3) {
            dsts[ma][0] = map_row(r);
            dsts[ma][1] = map_row(r + 8);
            or0 = (size_t)dsts[ma][0] * N;
            or1 = (size_t)dsts[ma][1] * N;
        } else {
            or0 = (size_t)r * N;
            or1 = or0 + (size_t)8 * N;
        }
        float ps0 = 0.0f, pq0 = 0.0f, ps1 = 0.0f, pq1 = 0.0f;
        #pragma unroll
        for (int na = 0; na < 8; na++) {
            int c = col0 + wcol * 64 + na * 8 + tig * 2;
            float b0v = bias[c], b1v = bias[c + 1];
            float v00 = acc[ma][na][0] + b0v;
            float v01 = acc[ma][na][1] + b1v;
            float v10 = acc[ma][na][2] + b0v;
            float v11 = acc[ma][na][3] + b1v;
            if (EPI == 1) {
                v00 = 0.5f * v00 * (1.0f + erff(v00 * 0.70710678118654752f));
                v01 = 0.5f * v01 * (1.0f + erff(v01 * 0.70710678118654752f));
                v10 = 0.5f * v10 * (1.0f + erff(v10 * 0.70710678118654752f));
                v11 = 0.5f * v11 * (1.0f + erff(v11 * 0.70710678118654752f));
            } else if (EPI == 2 || EPI == 3) {
                v00 += resid[or0 + c];     v01 += resid[or0 + c + 1];
                v10 += resid[or1 + c];     v11 += resid[or1 + c + 1];
            }
            if (EPI == 3) {
                ps0 += v00 + v01; pq0 += v00 * v00 + v01 * v01;
                ps1 += v10 + v11; pq1 += v10 * v10 + v11 * v11;
                acc[ma][na][0] = v00; acc[ma][na][1] = v01;
                acc[ma][na][2] = v10; acc[ma][na][3] = v11;
            }
            if (sizeof(CT) == 2) {
                *(uint32_t*)((__nv_bfloat16*)C + or0 + c) = pack_bf2(v00, v01);
                *(uint32_t*)((__nv_bfloat16*)C + or1 + c) = pack_bf2(v10, v11);
            } else {
                *(float2*)((float*)C + or0 + c) = make_float2(v00, v01);
                *(float2*)((float*)C + or1 + c) = make_float2(v10, v11);
            }
        }
        if (EPI == 3) {
            atomicAdd(&s_mu[rl0], ps0);     atomicAdd(&s_sq[rl0], pq0);
            atomicAdd(&s_mu[rl0 + 8], ps1); atomicAdd(&s_sq[rl0 + 8], pq1);
        }
    }

    if (EPI == 3) {
        __syncthreads();
        #pragma unroll
        for (int ma = 0; ma < 2; ma++) {
            int rl0 = wrow * 32 + ma * 16 + gid;
            float m0 = s_mu[rl0] * 0.0078125f;
            float m1 = s_mu[rl0 + 8] * 0.0078125f;
            float rs0 = rsqrtf(s_sq[rl0] * 0.0078125f - m0 * m0 + 1e-5f);
            float rs1 = rsqrtf(s_sq[rl0 + 8] * 0.0078125f - m1 * m1 + 1e-5f);
            size_t y0 = (size_t)dsts[ma][0] * 128;
            size_t y1 = (size_t)dsts[ma][1] * 128;
            #pragma unroll
            for (int na = 0; na < 8; na++) {
                int c = wcol * 64 + na * 8 + tig * 2;   // col0 == 0 for proj
                float g0 = g2[c], g1 = g2[c + 1];
                float bb0 = b2[c], bb1 = b2[c + 1];
                float y00 = (acc[ma][na][0] - m0) * rs0 * g0 + bb0;
                float y01 = (acc[ma][na][1] - m0) * rs0 * g1 + bb1;
                float y10 = (acc[ma][na][2] - m1) * rs1 * g0 + bb0;
                float y11 = (acc[ma][na][3] - m1) * rs1 * g1 + bb1;
                *(uint32_t*)(P_YWIN + y0 + c) = pack_bf2(y00, y01);
                *(uint32_t*)(P_YWIN + y1 + c) = pack_bf2(y10, y11);
            }
        }
    }
}

__global__ void __launch_bounds__(256) k_qkv(const float* __restrict__ b) {
    tgemm_body<0>(P_YWIN, g_wqkv, b, P_QKV, (const float*)nullptr,
                  (const float*)nullptr, (const float*)nullptr, 128, 384);
}
__global__ void __launch_bounds__(256) k_proj(const float* __restrict__ b,
                                              const float* __restrict__ x,
                                              const float* __restrict__ g2,
                                              const float* __restrict__ b2) {
    tgemm_body<3>(P_ATT, g_wproj, b, P_X1, x, g2, b2, 128, 128);
}
__global__ void __launch_bounds__(256) k_fc1(const float* __restrict__ b) {
    tgemm_body<1>(P_YWIN, g_wfc1, b, P_HID, (const float*)nullptr,
                  (const float*)nullptr, (const float*)nullptr, 128, 512);
}
__global__ void __launch_bounds__(256) k_fc2(const float* __restrict__ b,
                                             float* __restrict__ out) {
    tgemm_body<2>(P_HID, g_wfc2, b, out, P_X1,
                  (const float*)nullptr, (const float*)nullptr, 512, 128);
}

// ---------------------------------------------------------------------------
// Attention: one block per (window, head). N=49 tokens, head_dim=32.
// ---------------------------------------------------------------------------
__global__ void __launch_bounds__(128) k_attn(const float* __restrict__ rpb) {
    __shared__ float qs[49][33], ks[49][33], vs[49][33];
    __shared__ float sc[49][52];
    __shared__ float bias_s[169];
    __shared__ int   rid[49];

    int wh   = blockIdx.x;
    int win  = wh >> 2;
    int head = wh & 3;
    int widx = win & 63;
    int wi = widx >> 3, wj = widx & 7;
    int tid = threadIdx.x;

    const __nv_bfloat16* base = P_QKV + (size_t)(win * 49) * 384 + head * 32;
    for (int idx = tid; idx < 49 * 32; idx += 128) {
        int t = idx >> 5, d = idx & 31;
        const __nv_bfloat16* p = base + (size_t)t * 384 + d;
        qs[t][d] = __bfloat162float(p[0]) * HSCALE;
        ks[t][d] = __bfloat162float(p[128]);
        vs[t][d] = __bfloat162float(p[256]);
    }
    for (int idx = tid; idx < 169; idx += 128) bias_s[idx] = rpb[idx * 4 + head];
    if (tid < 49) {
        int r = wi * 7 + tid / 7;
        int c = wj * 7 + tid % 7;
        int rh = (r < 49) ? 0 : ((r < 53) ? 1 : 2);
        int rw = (c < 49) ? 0 : ((c < 53) ? 1 : 2);
        rid[tid] = rh * 3 + rw;
    }
    __syncthreads();

    for (int idx = tid; idx < 49 * 49; idx += 128) {
        int i = idx / 49, j = idx - i * 49;
        float s = 0.0f;
        #pragma unroll
        for (int d = 0; d < 32; d++) s = fmaf(qs[i][d], ks[j][d], s);
        int dr = i / 7 - j / 7 + 6;
        int dc = i % 7 - j % 7 + 6;
        s += bias_s[dr * 13 + dc];
        if (rid[i] != rid[j]) s -= 100.0f;
        sc[i][j] = s;
    }
    __syncthreads();

    if (tid < 49) {
        float mx = -1e30f;
        #pragma unroll 7
        for (int j = 0; j < 49; j++) mx = fmaxf(mx, sc[tid][j]);
        float sum = 0.0f;
        #pragma unroll 7
        for (int j = 0; j < 49; j++) {
            float e = __expf(sc[tid][j] - mx);
            sc[tid][j] = e;
            sum += e;
        }
        float inv = 1.0f / sum;
        #pragma unroll 7
        for (int j = 0; j < 49; j++) sc[tid][j] *= inv;
    }
    __syncthreads();

    for (int idx = tid; idx < 49 * 32; idx += 128) {
        int i = idx >> 5, d = idx & 31;
        float s = 0.0f;
        #pragma unroll 7
        for (int j = 0; j < 49; j++) s = fmaf(sc[i][j], vs[j][d], s);
        P_ATT[(size_t)(win * 49 + i) * 128 + head * 32 + d] = __float2bfloat16(s);
    }
}

// ---------------------------------------------------------------------------
extern "C" void kernel_launch(void* const* d_in, const int* in_sizes, int n_in,
                              void* d_out, int out_size) {
    const float* x      = (const float*)d_in[0];
    const float* n1g    = (const float*)d_in[1];
    const float* n1b    = (const float*)d_in[2];
    const float* qkv_w  = (const float*)d_in[3];
    const float* qkv_b  = (const float*)d_in[4];
    const float* rpb    = (const float*)d_in[5];
    const float* proj_w = (const float*)d_in[6];
    const float* proj_b = (const float*)d_in[7];
    const float* n2g    = (const float*)d_in[8];
    const float* n2b    = (const float*)d_in[9];
    const float* fc1_w  = (const float*)d_in[10];
    const float* fc1_b  = (const float*)d_in[11];
    const float* fc2_w  = (const float*)d_in[12];
    const float* fc2_b  = (const float*)d_in[13];
    float* out = (float*)d_out;

    k_convw<<<768, 256>>>(qkv_w, proj_w, fc1_w, fc2_w);
    k_ln1<<<M_TOT / 8, 256>>>(x, n1g, n1b);
    k_qkv<<<dim3(3, M_TOT / 128), 256>>>(qkv_b);
    k_attn<<<(M_TOT / 49) * 4, 128>>>(rpb);
    k_proj<<<dim3(1, M_TOT / 128), 256>>>(proj_b, x, n2g, n2b);
    k_fc1<<<dim3(4, M_TOT / 128), 256>>>(fc1_b);
    k_fc2<<<dim3(1, M_TOT / 128), 256>>>(fc2_b, out);
}

// round 12
// speedup vs baseline: 4.1725x; 1.8338x over previous
#include <cuda_runtime.h>
#include <cuda_bf16.h>
#include <math.h>
#include <stdint.h>

// ---------------------------------------------------------------------------
// Swin Transformer block, B=64, H=W=56, DIM=128, HEADS=4, HEAD_DIM=32, WS=7,
// SHIFT=3, N=49, NW=64, HIDDEN=512.  M_TOT = 200704 tokens.
//
//   0. convw      : fp32 weights -> bf16 transposed [N][K]
//   1. ln1_gather : LN(x) + shift + window partition -> ywin (bf16)
//   2. qkv GEMM   : ywin @ qkv_w + b -> qkv (bf16)
//   3. attention  : mma-based softmax(qk^T+bias+mask) @ v -> att (bf16)
//   4. proj GEMM  : att @ proj_w + b, scatter + resid x -> x1 (fp32) + fused LN2
//   5. fc1 GEMM   : ywin @ fc1_w + b, exact GELU -> hid (bf16)
//   6. fc2 GEMM   : hid @ fc2_w + b + resid x1 -> d_out (fp32)
// ---------------------------------------------------------------------------

#define M_TOT 200704
#define HSCALE 0.17677669529663687f   /* 32^-0.5 */

__device__ float g_s[(size_t)M_TOT * 448];

#define P_YWIN ((__nv_bfloat16*)(g_s))
#define P_QKV  ((__nv_bfloat16*)(g_s + (size_t)M_TOT * 64))
#define P_ATT  ((__nv_bfloat16*)(g_s + (size_t)M_TOT * 256))
#define P_HID  ((__nv_bfloat16*)(g_s + (size_t)M_TOT * 64))
#define P_X1   (g_s + (size_t)M_TOT * 320)

__device__ __nv_bfloat16 g_wqkv[384 * 128];
__device__ __nv_bfloat16 g_wproj[128 * 128];
__device__ __nv_bfloat16 g_wfc1[512 * 128];
__device__ __nv_bfloat16 g_wfc2[128 * 512];

__device__ __forceinline__ int map_row(int m) {
    int win = m / 49;
    int t   = m - win * 49;
    int img  = win >> 6;
    int widx = win & 63;
    int tr = t / 7;
    int hs = (widx >> 3) * 7 + tr;
    int ws = (widx & 7) * 7 + (t - tr * 7);
    int hh = hs + 3; if (hh >= 56) hh -= 56;
    int ww = ws + 3; if (ww >= 56) ww -= 56;
    return img * 3136 + hh * 56 + ww;
}

__device__ __forceinline__ uint32_t pack_bf2(float lo, float hi) {
    uint32_t r;
    asm("cvt.rn.bf16x2.f32 %0, %1, %2;" : "=r"(r) : "f"(hi), "f"(lo));
    return r;
}

// ---------------------------------------------------------------------------
__global__ void k_convw(const float* __restrict__ qkv_w, const float* __restrict__ proj_w,
                        const float* __restrict__ fc1_w, const float* __restrict__ fc2_w) {
    int i = blockIdx.x * blockDim.x + threadIdx.x;
    if (i < 49152) {
        int n = i / 128, k = i % 128;
        g_wqkv[i] = __float2bfloat16(qkv_w[k * 384 + n]);
    } else if (i < 65536) {
        int j = i - 49152; int n = j / 128, k = j % 128;
        g_wproj[j] = __float2bfloat16(proj_w[k * 128 + n]);
    } else if (i < 131072) {
        int j = i - 65536; int n = j / 128, k = j % 128;
        g_wfc1[j] = __float2bfloat16(fc1_w[k * 512 + n]);
    } else if (i < 196608) {
        int j = i - 131072; int n = j / 512, k = j % 512;
        g_wfc2[j] = __float2bfloat16(fc2_w[k * 128 + n]);
    }
}

// ---------------------------------------------------------------------------
__global__ void k_ln1(const float* __restrict__ X, const float* __restrict__ g,
                      const float* __restrict__ b) {
    int w = (int)((blockIdx.x * blockDim.x + threadIdx.x) >> 5);
    if (w >= M_TOT) return;
    int lane = threadIdx.x & 31;
    const float* xp = X + (size_t)map_row(w) * 128;
    float v0 = xp[lane], v1 = xp[lane + 32], v2 = xp[lane + 64], v3 = xp[lane + 96];
    float s = v0 + v1 + v2 + v3;
    #pragma unroll
    for (int o = 16; o; o >>= 1) s += __shfl_xor_sync(0xffffffffu, s, o);
    float mean = s * 0.0078125f;
    float d0 = v0 - mean, d1 = v1 - mean, d2 = v2 - mean, d3 = v3 - mean;
    float vv = d0 * d0 + d1 * d1 + d2 * d2 + d3 * d3;
    #pragma unroll
    for (int o = 16; o; o >>= 1) vv += __shfl_xor_sync(0xffffffffu, vv, o);
    float rstd = rsqrtf(vv * 0.0078125f + 1e-5f);
    __nv_bfloat16* yp = P_YWIN + (size_t)w * 128;
    yp[lane]      = __float2bfloat16(d0 * rstd * g[lane]      + b[lane]);
    yp[lane + 32] = __float2bfloat16(d1 * rstd * g[lane + 32] + b[lane + 32]);
    yp[lane + 64] = __float2bfloat16(d2 * rstd * g[lane + 64] + b[lane + 64]);
    yp[lane + 96] = __float2bfloat16(d3 * rstd * g[lane + 96] + b[lane + 96]);
}

// ---------------------------------------------------------------------------
__device__ __forceinline__ void mma_bf16(float* c, const uint32_t* a, const uint32_t* b) {
    asm volatile(
        "mma.sync.aligned.m16n8k16.row.col.f32.bf16.bf16.f32 "
        "{%0,%1,%2,%3}, {%4,%5,%6,%7}, {%8,%9}, {%0,%1,%2,%3};"
        : "+f"(c[0]), "+f"(c[1]), "+f"(c[2]), "+f"(c[3])
        : "r"(a[0]), "r"(a[1]), "r"(a[2]), "r"(a[3]), "r"(b[0]), "r"(b[1]));
}

__device__ __forceinline__ void ldsm4(uint32_t* r, uint32_t a) {
    asm volatile("ldmatrix.sync.aligned.m8n8.x4.shared.b16 {%0,%1,%2,%3}, [%4];"
                 : "=r"(r[0]), "=r"(r[1]), "=r"(r[2]), "=r"(r[3]) : "r"(a));
}

__device__ __forceinline__ void cp16(uint32_t dst, const void* src) {
    asm volatile("cp.async.ca.shared.global [%0], [%1], 16;" :: "r"(dst), "l"(src));
}
#define CP_COMMIT() asm volatile("cp.async.commit_group;")
#define CP_WAIT0()  asm volatile("cp.async.wait_group 0;")

template <int EPI, typename CT>
__device__ __forceinline__ void tgemm_body(const __nv_bfloat16* __restrict__ A,
                                           const __nv_bfloat16* __restrict__ W,
                                           const float* __restrict__ bias,
                                           CT* __restrict__ C,
                                           const float* __restrict__ resid,
                                           const float* __restrict__ g2,
                                           const float* __restrict__ b2,
                                           int K, int N) {
    __shared__ uint32_t As[2][128][12];
    __shared__ uint32_t Bs[2][128][12];
    __shared__ float s_mu[128], s_sq[128];

    int tid  = threadIdx.x;
    int row0 = blockIdx.y * 128;
    int col0 = blockIdx.x * 128;
    int lane = tid & 31;
    int wid  = tid >> 5;
    int gid  = lane >> 2;
    int tig  = lane & 3;
    int wrow = wid >> 1;
    int wcol = wid & 1;

    const int BUFB = 128 * 12 * 4;
    uint32_t asb = (uint32_t)__cvta_generic_to_shared(&As[0][0][0]);
    uint32_t bsb = (uint32_t)__cvta_generic_to_shared(&Bs[0][0][0]);

    int srow = tid >> 1, sh = tid & 1;
    const __nv_bfloat16* Ap = A + (size_t)(row0 + srow) * K + sh * 8;
    const __nv_bfloat16* Wp = W + (size_t)(col0 + srow) * K + sh * 8;
    uint32_t aDst = asb + (uint32_t)(srow * 12 + sh * 4) * 4;
    uint32_t bDst = bsb + (uint32_t)(srow * 12 + sh * 4) * 4;

    int rr  = lane & 7;
    int l8  = (lane >> 3) & 1;
    int l16 = lane >> 4;
    uint32_t aF = asb + (uint32_t)(((wrow * 32 + l8 * 8 + rr) * 12 + l16 * 4)) * 4;
    uint32_t bF = bsb + (uint32_t)(((wcol * 64 + l16 * 8 + rr) * 12 + l8 * 4)) * 4;

    float acc[2][8][4];
    #pragma unroll
    for (int ma = 0; ma < 2; ma++)
        #pragma unroll
        for (int na = 0; na < 8; na++)
            #pragma unroll
            for (int q = 0; q < 4; q++) acc[ma][na][q] = 0.0f;

    cp16(aDst, Ap);
    cp16(bDst, Wp);
    CP_COMMIT();
    CP_WAIT0();
    __syncthreads();

    int nIter = K >> 4;
    for (int it = 0; it < nIter; it++) {
        int buf = it & 1;
        bool more = (it + 1 < nIter);
        if (more) {
            int k0 = (it + 1) << 4;
            uint32_t off = (uint32_t)(buf ^ 1) * BUFB;
            cp16(aDst + off, Ap + k0);
            cp16(bDst + off, Wp + k0);
            CP_COMMIT();
        }

        uint32_t boff = (uint32_t)buf * BUFB;
        uint32_t af[2][4];
        ldsm4(af[0], aF + boff);
        ldsm4(af[1], aF + boff + 16 * 48);
        uint32_t bf[8][2];
        #pragma unroll
        for (int q = 0; q < 4; q++) {
            uint32_t bq[4];
            ldsm4(bq, bF + boff + (uint32_t)q * 16 * 48);
            bf[2 * q][0] = bq[0]; bf[2 * q][1] = bq[1];
            bf[2 * q + 1][0] = bq[2]; bf[2 * q + 1][1] = bq[3];
        }
        #pragma unroll
        for (int ma = 0; ma < 2; ma++)
            #pragma unroll
            for (int na = 0; na < 8; na++)
                mma_bf16(acc[ma][na], af[ma], bf[na]);

        if (more) {
            CP_WAIT0();
            __syncthreads();
        }
    }

    if (EPI == 3) {
        if (tid < 128) { s_mu[tid] = 0.0f; s_sq[tid] = 0.0f; }
        __syncthreads();
    }

    int dsts[2][2];
    #pragma unroll
    for (int ma = 0; ma < 2; ma++) {
        int rl0 = wrow * 32 + ma * 16 + gid;
        int r = row0 + rl0;
        size_t or0, or1;
        if (EPI == 3) {
            dsts[ma][0] = map_row(r);
            dsts[ma][1] = map_row(r + 8);
            or0 = (size_t)dsts[ma][0] * N;
            or1 = (size_t)dsts[ma][1] * N;
        } else {
            or0 = (size_t)r * N;
            or1 = or0 + (size_t)8 * N;
        }
        float ps0 = 0.0f, pq0 = 0.0f, ps1 = 0.0f, pq1 = 0.0f;
        #pragma unroll
        for (int na = 0; na < 8; na++) {
            int c = col0 + wcol * 64 + na * 8 + tig * 2;
            float b0v = bias[c], b1v = bias[c + 1];
            float v00 = acc[ma][na][0] + b0v;
            float v01 = acc[ma][na][1] + b1v;
            float v10 = acc[ma][na][2] + b0v;
            float v11 = acc[ma][na][3] + b1v;
            if (EPI == 1) {
                v00 = 0.5f * v00 * (1.0f + erff(v00 * 0.70710678118654752f));
                v01 = 0.5f * v01 * (1.0f + erff(v01 * 0.70710678118654752f));
                v10 = 0.5f * v10 * (1.0f + erff(v10 * 0.70710678118654752f));
                v11 = 0.5f * v11 * (1.0f + erff(v11 * 0.70710678118654752f));
            } else if (EPI == 2 || EPI == 3) {
                v00 += resid[or0 + c];     v01 += resid[or0 + c + 1];
                v10 += resid[or1 + c];     v11 += resid[or1 + c + 1];
            }
            if (EPI == 3) {
                ps0 += v00 + v01; pq0 += v00 * v00 + v01 * v01;
                ps1 += v10 + v11; pq1 += v10 * v10 + v11 * v11;
                acc[ma][na][0] = v00; acc[ma][na][1] = v01;
                acc[ma][na][2] = v10; acc[ma][na][3] = v11;
            }
            if (sizeof(CT) == 2) {
                *(uint32_t*)((__nv_bfloat16*)C + or0 + c) = pack_bf2(v00, v01);
                *(uint32_t*)((__nv_bfloat16*)C + or1 + c) = pack_bf2(v10, v11);
            } else {
                *(float2*)((float*)C + or0 + c) = make_float2(v00, v01);
                *(float2*)((float*)C + or1 + c) = make_float2(v10, v11);
            }
        }
        if (EPI == 3) {
            atomicAdd(&s_mu[rl0], ps0);     atomicAdd(&s_sq[rl0], pq0);
            atomicAdd(&s_mu[rl0 + 8], ps1); atomicAdd(&s_sq[rl0 + 8], pq1);
        }
    }

    if (EPI == 3) {
        __syncthreads();
        #pragma unroll
        for (int ma = 0; ma < 2; ma++) {
            int rl0 = wrow * 32 + ma * 16 + gid;
            float m0 = s_mu[rl0] * 0.0078125f;
            float m1 = s_mu[rl0 + 8] * 0.0078125f;
            float rs0 = rsqrtf(s_sq[rl0] * 0.0078125f - m0 * m0 + 1e-5f);
            float rs1 = rsqrtf(s_sq[rl0 + 8] * 0.0078125f - m1 * m1 + 1e-5f);
            size_t y0 = (size_t)dsts[ma][0] * 128;
            size_t y1 = (size_t)dsts[ma][1] * 128;
            #pragma unroll
            for (int na = 0; na < 8; na++) {
                int c = wcol * 64 + na * 8 + tig * 2;
                float g0 = g2[c], g1 = g2[c + 1];
                float bb0 = b2[c], bb1 = b2[c + 1];
                float y00 = (acc[ma][na][0] - m0) * rs0 * g0 + bb0;
                float y01 = (acc[ma][na][1] - m0) * rs0 * g1 + bb1;
                float y10 = (acc[ma][na][2] - m1) * rs1 * g0 + bb0;
                float y11 = (acc[ma][na][3] - m1) * rs1 * g1 + bb1;
                *(uint32_t*)(P_YWIN + y0 + c) = pack_bf2(y00, y01);
                *(uint32_t*)(P_YWIN + y1 + c) = pack_bf2(y10, y11);
            }
        }
    }
}

__global__ void __launch_bounds__(256) k_qkv(const float* __restrict__ b) {
    tgemm_body<0>(P_YWIN, g_wqkv, b, P_QKV, (const float*)nullptr,
                  (const float*)nullptr, (const float*)nullptr, 128, 384);
}
__global__ void __launch_bounds__(256) k_proj(const float* __restrict__ b,
                                              const float* __restrict__ x,
                                              const float* __restrict__ g2,
                                              const float* __restrict__ b2) {
    tgemm_body<3>(P_ATT, g_wproj, b, P_X1, x, g2, b2, 128, 128);
}
__global__ void __launch_bounds__(256) k_fc1(const float* __restrict__ b) {
    tgemm_body<1>(P_YWIN, g_wfc1, b, P_HID, (const float*)nullptr,
                  (const float*)nullptr, (const float*)nullptr, 128, 512);
}
__global__ void __launch_bounds__(256) k_fc2(const float* __restrict__ b,
                                             float* __restrict__ out) {
    tgemm_body<2>(P_HID, g_wfc2, b, out, P_X1,
                  (const float*)nullptr, (const float*)nullptr, 512, 128);
}

// ---------------------------------------------------------------------------
// mma attention: block = (window, head), 4 warps; warp w owns Q rows [16w,16w+16).
// S (64x64, padded from 49x49) lives entirely in C-fragments; softmax in
// registers; P re-packed in-register as A-fragments for P@V.
// Qs/Ks: [64][20 words] bf16 rows (pad-20 -> conflict-free ldsm).
// Vt: transposed V [32 d][36-word rows] (pad-36), zeroed for j>=49.
// ---------------------------------------------------------------------------
__global__ void __launch_bounds__(128) k_attn(const float* __restrict__ rpb) {
    __shared__ uint32_t Qs[64][20];
    __shared__ uint32_t Ks[64][20];
    __shared__ uint32_t Vt[32][36];
    __shared__ float bias_s[169];
    __shared__ int rid[49];

    int wh  = blockIdx.x;
    int win = wh >> 2, head = wh & 3;
    int widx = win & 63;
    int wi = widx >> 3, wj = widx & 7;
    int tid = threadIdx.x;
    int lane = tid & 31, wid = tid >> 5;

    const __nv_bfloat16* base = P_QKV + (size_t)(win * 49) * 384 + head * 32;

    for (int i = tid; i < 32 * 36; i += 128) (&Vt[0][0])[i] = 0;
    for (int i = tid; i < 196; i += 128) {
        int t = i >> 2, q4 = i & 3;
        *(uint4*)&Qs[t][q4 * 4] = *(const uint4*)(base + (size_t)t * 384 + q4 * 8);
        *(uint4*)&Ks[t][q4 * 4] = *(const uint4*)(base + 128 + (size_t)t * 384 + q4 * 8);
    }
    for (int i = tid; i < 169; i += 128) bias_s[i] = rpb[i * 4 + head];
    if (tid < 49) {
        int r = wi * 7 + tid / 7, c = wj * 7 + tid % 7;
        int rh = (r < 49) ? 0 : ((r < 53) ? 1 : 2);
        int rw = (c < 49) ? 0 : ((c < 53) ? 1 : 2);
        rid[tid] = rh * 3 + rw;
    }
    __syncthreads();          // Vt zero complete before transposed writes
    for (int i = tid; i < 196; i += 128) {
        int t = i >> 2, q4 = i & 3;
        uint4 vv = *(const uint4*)(base + 256 + (size_t)t * 384 + q4 * 8);
        __nv_bfloat16 tmp[8];
        *(uint4*)tmp = vv;
        __nv_bfloat16* vt = (__nv_bfloat16*)&Vt[0][0];
        #pragma unroll
        for (int q = 0; q < 8; q++) vt[(q4 * 8 + q) * 72 + t] = tmp[q];
    }
    __syncthreads();

    uint32_t qsb = (uint32_t)__cvta_generic_to_shared(&Qs[0][0]);
    uint32_t ksb = (uint32_t)__cvta_generic_to_shared(&Ks[0][0]);
    uint32_t vtb = (uint32_t)__cvta_generic_to_shared(&Vt[0][0]);
    int rr = lane & 7, l8 = (lane >> 3) & 1, l16 = lane >> 4;
    int gid = lane >> 2, tig = lane & 3;
    int warpm = wid;

    // ---- S = Q @ K^T ----
    float accS[8][4];
    #pragma unroll
    for (int na = 0; na < 8; na++)
        #pragma unroll
        for (int q = 0; q < 4; q++) accS[na][q] = 0.0f;

    uint32_t aQ[2][4];
    uint32_t aAddr = qsb + (uint32_t)(((warpm * 16 + l8 * 8 + rr) * 20 + l16 * 4)) * 4;
    ldsm4(aQ[0], aAddr);        // k 0..15
    ldsm4(aQ[1], aAddr + 32);   // k 16..31
    #pragma unroll
    for (int ks = 0; ks < 2; ks++) {
        #pragma unroll
        for (int nb = 0; nb < 4; nb++) {
            uint32_t bq[4];
            uint32_t bAddr = ksb + (uint32_t)(((nb * 16 + l16 * 8 + rr) * 20 + ks * 8 + l8 * 4)) * 4;
            ldsm4(bq, bAddr);
            uint32_t b01[2] = {bq[0], bq[1]};
            uint32_t b23[2] = {bq[2], bq[3]};
            mma_bf16(accS[nb * 2],     aQ[ks], b01);
            mma_bf16(accS[nb * 2 + 1], aQ[ks], b23);
        }
    }

    // ---- bias + mask + softmax (registers) ----
    int i0 = warpm * 16 + gid, i1 = i0 + 8;
    bool ok0 = i0 < 49, ok1 = i1 < 49;
    int ib0 = ok0 ? (i0 / 7) * 13 + i0 % 7 + 84 : 84;
    int ib1 = ok1 ? (i1 / 7) * 13 + i1 % 7 + 84 : 84;
    int ri0 = ok0 ? rid[i0] : 0;
    int ri1 = ok1 ? rid[i1] : 0;

    float mx0 = -1e30f, mx1 = -1e30f;
    #pragma unroll
    for (int na = 0; na < 8; na++) {
        int j0 = na * 8 + tig * 2, j1 = j0 + 1;
        bool v0 = j0 < 49, v1 = j1 < 49;
        int jb0 = v0 ? (j0 / 7) * 13 + j0 % 7 : 0;
        int jb1 = v1 ? (j1 / 7) * 13 + j1 % 7 : 0;
        int rj0 = v0 ? rid[j0] : -1;
        int rj1 = v1 ? rid[j1] : -1;
        accS[na][0] = (ok0 && v0) ? accS[na][0] * HSCALE + bias_s[ib0 - jb0] + ((ri0 != rj0) ? -100.0f : 0.0f) : -1e30f;
        accS[na][1] = (ok0 && v1) ? accS[na][1] * HSCALE + bias_s[ib0 - jb1] + ((ri0 != rj1) ? -100.0f : 0.0f) : -1e30f;
        accS[na][2] = (ok1 && v0) ? accS[na][2] * HSCALE + bias_s[ib1 - jb0] + ((ri1 != rj0) ? -100.0f : 0.0f) : -1e30f;
        accS[na][3] = (ok1 && v1) ? accS[na][3] * HSCALE + bias_s[ib1 - jb1] + ((ri1 != rj1) ? -100.0f : 0.0f) : -1e30f;
        mx0 = fmaxf(mx0, fmaxf(accS[na][0], accS[na][1]));
        mx1 = fmaxf(mx1, fmaxf(accS[na][2], accS[na][3]));
    }
    mx0 = fmaxf(mx0, __shfl_xor_sync(0xffffffffu, mx0, 1));
    mx0 = fmaxf(mx0, __shfl_xor_sync(0xffffffffu, mx0, 2));
    mx1 = fmaxf(mx1, __shfl_xor_sync(0xffffffffu, mx1, 1));
    mx1 = fmaxf(mx1, __shfl_xor_sync(0xffffffffu, mx1, 2));

    float sum0 = 0.0f, sum1 = 0.0f;
    #pragma unroll
    for (int na = 0; na < 8; na++) {
        accS[na][0] = __expf(accS[na][0] - mx0); sum0 += accS[na][0];
        accS[na][1] = __expf(accS[na][1] - mx0); sum0 += accS[na][1];
        accS[na][2] = __expf(accS[na][2] - mx1); sum1 += accS[na][2];
        accS[na][3] = __expf(accS[na][3] - mx1); sum1 += accS[na][3];
    }
    sum0 += __shfl_xor_sync(0xffffffffu, sum0, 1);
    sum0 += __shfl_xor_sync(0xffffffffu, sum0, 2);
    sum1 += __shfl_xor_sync(0xffffffffu, sum1, 1);
    sum1 += __shfl_xor_sync(0xffffffffu, sum1, 2);
    float inv0 = 1.0f / sum0, inv1 = 1.0f / sum1;

    // ---- O = P @ V  (P re-packed from C-frags to A-frags in registers) ----
    float accO[4][4];
    #pragma unroll
    for (int na = 0; na < 4; na++)
        #pragma unroll
        for (int q = 0; q < 4; q++) accO[na][q] = 0.0f;

    #pragma unroll
    for (int ks = 0; ks < 4; ks++) {
        uint32_t aP[4];
        aP[0] = pack_bf2(accS[2 * ks][0],     accS[2 * ks][1]);
        aP[1] = pack_bf2(accS[2 * ks][2],     accS[2 * ks][3]);
        aP[2] = pack_bf2(accS[2 * ks + 1][0], accS[2 * ks + 1][1]);
        aP[3] = pack_bf2(accS[2 * ks + 1][2], accS[2 * ks + 1][3]);
        #pragma unroll
        for (int nb = 0; nb < 2; nb++) {
            uint32_t bq[4];
            uint32_t bAddr = vtb + (uint32_t)(((nb * 16 + l16 * 8 + rr) * 36 + ks * 8 + l8 * 4)) * 4;
            ldsm4(bq, bAddr);
            uint32_t b01[2] = {bq[0], bq[1]};
            uint32_t b23[2] = {bq[2], bq[3]};
            mma_bf16(accO[nb * 2],     aP, b01);
            mma_bf16(accO[nb * 2 + 1], aP, b23);
        }
    }

    // ---- store (normalize by 1/sum at write) ----
    __nv_bfloat16* ob = P_ATT + (size_t)(win * 49) * 128 + head * 32;
    if (ok0) {
        #pragma unroll
        for (int na = 0; na < 4; na++) {
            int d = na * 8 + tig * 2;
            *(uint32_t*)(ob + (size_t)i0 * 128 + d) =
                pack_bf2(accO[na][0] * inv0, accO[na][1] * inv0);
        }
    }
    if (ok1) {
        #pragma unroll
        for (int na = 0; na < 4; na++) {
            int d = na * 8 + tig * 2;
            *(uint32_t*)(ob + (size_t)i1 * 128 + d) =
                pack_bf2(accO[na][2] * inv1, accO[na][3] * inv1);
        }
    }
}

// ---------------------------------------------------------------------------
extern "C" void kernel_launch(void* const* d_in, const int* in_sizes, int n_in,
                              void* d_out, int out_size) {
    const float* x      = (const float*)d_in[0];
    const float* n1g    = (const float*)d_in[1];
    const float* n1b    = (const float*)d_in[2];
    const float* qkv_w  = (const float*)d_in[3];
    const float* qkv_b  = (const float*)d_in[4];
    const float* rpb    = (const float*)d_in[5];
    const float* proj_w = (const float*)d_in[6];
    const float* proj_b = (const float*)d_in[7];
    const float* n2g    = (const float*)d_in[8];
    const float* n2b    = (const float*)d_in[9];
    const float* fc1_w  = (const float*)d_in[10];
    const float* fc1_b  = (const float*)d_in[11];
    const float* fc2_w  = (const float*)d_in[12];
    const float* fc2_b  = (const float*)d_in[13];
    float* out = (float*)d_out;

    k_convw<<<768, 256>>>(qkv_w, proj_w, fc1_w, fc2_w);
    k_ln1<<<M_TOT / 8, 256>>>(x, n1g, n1b);
    k_qkv<<<dim3(3, M_TOT / 128), 256>>>(qkv_b);
    k_attn<<<(M_TOT / 49) * 4, 128>>>(rpb);
    k_proj<<<dim3(1, M_TOT / 128), 256>>>(proj_b, x, n2g, n2b);
    k_fc1<<<dim3(4, M_TOT / 128), 256>>>(fc1_b);
    k_fc2<<<dim3(1, M_TOT / 128), 256>>>(fc2_b, out);
}